// round 1
// baseline (speedup 1.0000x reference)
#include <cuda_runtime.h>
#include <math.h>

// ---------------------------------------------------------------------------
// MoE grouped MLP: T=4096 tokens, H=2048 hidden, I=1408 intermediate,
// E=8 experts, top-K=2.
//   rows = K*T = 8192 expanded rows, grouped by expert.
//   act  = silu(x @ gate_w[e]) * (x @ up_w[e])     [8192, I]
//   out[t] += prob * (act_row @ down_w[e])         [T, H]
// Round-1 baseline: fp32 SIMT tiled GEMMs + device-side permutation.
// ---------------------------------------------------------------------------

#define T_TOK 4096
#define H_DIM 2048
#define I_DIM 1408
#define N_EXP 8
#define TOPK  2
#define R_ROWS (T_TOK * TOPK)       // 8192

#define BM 128
#define BN 64
#define BK 16
#define MAX_TILES (R_ROWS / BM + N_EXP)   // 72 worst case

// ---- device-global scratch (no allocations allowed) ----
__device__ int   g_counts[N_EXP];
__device__ int   g_cursor[N_EXP];
__device__ int   g_tile_e[MAX_TILES];
__device__ int   g_tile_row0[MAX_TILES];
__device__ int   g_tile_rows[MAX_TILES];
__device__ int   g_num_tiles;
__device__ int   g_row_t[R_ROWS];         // source token per sorted row
__device__ float g_row_p[R_ROWS];         // router prob per sorted row
__device__ float g_act[R_ROWS * I_DIM];   // 46 MB intermediate activations

// ---------------------------------------------------------------------------
__global__ void k_zero_counts() {
    if (threadIdx.x < N_EXP) g_counts[threadIdx.x] = 0;
}

__global__ void k_hist(const int* __restrict__ sel) {
    int f = blockIdx.x * blockDim.x + threadIdx.x;
    if (f < R_ROWS) {
        int t = f % T_TOK;
        int k = f / T_TOK;
        atomicAdd(&g_counts[sel[t * TOPK + k]], 1);
    }
}

__global__ void k_prep() {
    // single thread: prefix sum over 8 experts + build ragged tile table
    int off = 0, nt = 0;
    for (int e = 0; e < N_EXP; ++e) {
        int c = g_counts[e];
        g_cursor[e] = off;
        for (int r0 = 0; r0 < c; r0 += BM) {
            g_tile_e[nt]    = e;
            g_tile_row0[nt] = off + r0;
            g_tile_rows[nt] = min(BM, c - r0);
            ++nt;
        }
        off += c;
    }
    g_num_tiles = nt;
}

__global__ void k_scatter(const int* __restrict__ sel,
                          const float* __restrict__ rw) {
    int f = blockIdx.x * blockDim.x + threadIdx.x;
    if (f < R_ROWS) {
        int t = f % T_TOK;
        int k = f / T_TOK;
        int e = sel[t * TOPK + k];
        int d = atomicAdd(&g_cursor[e], 1);
        g_row_t[d] = t;
        g_row_p[d] = rw[t * TOPK + k];
    }
}

__global__ void k_zero_out(float4* __restrict__ out, int n4) {
    int i = blockIdx.x * blockDim.x + threadIdx.x;
    if (i < n4) out[i] = make_float4(0.f, 0.f, 0.f, 0.f);
}

// ---------------------------------------------------------------------------
// GEMM1: fused gate+up.  C_g = A @ gate_w[e], C_u = A @ up_w[e],
// act = silu(C_g) * C_u.  A rows gathered from hidden_states via g_row_t.
// Block: BM x BN tile, 256 threads, 8x4 microtile per thread.
// ---------------------------------------------------------------------------
__global__ __launch_bounds__(256, 2)
void k_gemm1(const float* __restrict__ hid,
             const float* __restrict__ gw,
             const float* __restrict__ uw) {
    const int tile = blockIdx.x;
    if (tile >= g_num_tiles) return;
    const int e    = g_tile_e[tile];
    const int row0 = g_tile_row0[tile];
    const int rows = g_tile_rows[tile];
    const int n0   = blockIdx.y * BN;

    __shared__ float As[BK][BM];
    __shared__ float Bg[BK][BN];
    __shared__ float Bu[BK][BN];

    const int tid   = threadIdx.x;
    const int tx    = tid & 15;
    const int ty    = tid >> 4;
    const int rbase = ty * 8;
    const int cbase = tx * 4;

    const float* gwe = gw + (size_t)e * H_DIM * I_DIM;
    const float* uwe = uw + (size_t)e * H_DIM * I_DIM;

    // A-load mapping: each thread loads 2 float4s of the 128x16 A tile
    const int aidx  = tid * 2;
    const int ar0   = aidx >> 2,       akq0 = aidx & 3;
    const int ar1   = (aidx + 1) >> 2, akq1 = (aidx + 1) & 3;
    const int at0   = (ar0 < rows) ? g_row_t[row0 + ar0] : -1;
    const int at1   = (ar1 < rows) ? g_row_t[row0 + ar1] : -1;

    // B-load mapping: one float4 per thread per B matrix
    const int bkk = tid >> 4;
    const int bn  = (tid & 15) * 4;

    float accg[8][4], accu[8][4];
    #pragma unroll
    for (int i = 0; i < 8; ++i)
        #pragma unroll
        for (int j = 0; j < 4; ++j) { accg[i][j] = 0.f; accu[i][j] = 0.f; }

    for (int k0 = 0; k0 < H_DIM; k0 += BK) {
        float4 va = (at0 >= 0)
            ? *(const float4*)&hid[(size_t)at0 * H_DIM + k0 + akq0 * 4]
            : make_float4(0.f, 0.f, 0.f, 0.f);
        float4 vb = (at1 >= 0)
            ? *(const float4*)&hid[(size_t)at1 * H_DIM + k0 + akq1 * 4]
            : make_float4(0.f, 0.f, 0.f, 0.f);
        float4 vg = *(const float4*)&gwe[(size_t)(k0 + bkk) * I_DIM + n0 + bn];
        float4 vu = *(const float4*)&uwe[(size_t)(k0 + bkk) * I_DIM + n0 + bn];

        __syncthreads();   // previous iteration's compute done
        As[akq0 * 4 + 0][ar0] = va.x;
        As[akq0 * 4 + 1][ar0] = va.y;
        As[akq0 * 4 + 2][ar0] = va.z;
        As[akq0 * 4 + 3][ar0] = va.w;
        As[akq1 * 4 + 0][ar1] = vb.x;
        As[akq1 * 4 + 1][ar1] = vb.y;
        As[akq1 * 4 + 2][ar1] = vb.z;
        As[akq1 * 4 + 3][ar1] = vb.w;
        *(float4*)&Bg[bkk][bn] = vg;
        *(float4*)&Bu[bkk][bn] = vu;
        __syncthreads();

        #pragma unroll
        for (int kk = 0; kk < BK; ++kk) {
            float4 a0 = *(const float4*)&As[kk][rbase];
            float4 a1 = *(const float4*)&As[kk][rbase + 4];
            float4 g4 = *(const float4*)&Bg[kk][cbase];
            float4 u4 = *(const float4*)&Bu[kk][cbase];
            float a[8]  = {a0.x, a0.y, a0.z, a0.w, a1.x, a1.y, a1.z, a1.w};
            float gv[4] = {g4.x, g4.y, g4.z, g4.w};
            float uv[4] = {u4.x, u4.y, u4.z, u4.w};
            #pragma unroll
            for (int i = 0; i < 8; ++i)
                #pragma unroll
                for (int j = 0; j < 4; ++j) {
                    accg[i][j] += a[i] * gv[j];
                    accu[i][j] += a[i] * uv[j];
                }
        }
    }

    // epilogue: act = silu(g) * u
    #pragma unroll
    for (int i = 0; i < 8; ++i) {
        int r = rbase + i;
        if (r < rows) {
            float* dst = &g_act[(size_t)(row0 + r) * I_DIM + n0 + cbase];
            float4 o;
            float g, u;
            g = accg[i][0]; u = accu[i][0]; o.x = (g / (1.f + __expf(-g))) * u;
            g = accg[i][1]; u = accu[i][1]; o.y = (g / (1.f + __expf(-g))) * u;
            g = accg[i][2]; u = accu[i][2]; o.z = (g / (1.f + __expf(-g))) * u;
            g = accg[i][3]; u = accu[i][3]; o.w = (g / (1.f + __expf(-g))) * u;
            *(float4*)dst = o;
        }
    }
}

// ---------------------------------------------------------------------------
// GEMM2: down projection + weighted scatter-add into out.
//   C = act_rows @ down_w[e];  out[t, :] += prob * C_row
// ---------------------------------------------------------------------------
__global__ __launch_bounds__(256, 2)
void k_gemm2(const float* __restrict__ dw,
             float* __restrict__ out) {
    const int tile = blockIdx.x;
    if (tile >= g_num_tiles) return;
    const int e    = g_tile_e[tile];
    const int row0 = g_tile_row0[tile];
    const int rows = g_tile_rows[tile];
    const int n0   = blockIdx.y * BN;

    __shared__ float As[BK][BM];
    __shared__ float Bs[BK][BN];

    const int tid   = threadIdx.x;
    const int tx    = tid & 15;
    const int ty    = tid >> 4;
    const int rbase = ty * 8;
    const int cbase = tx * 4;

    const float* dwe = dw + (size_t)e * I_DIM * H_DIM;

    const int aidx = tid * 2;
    const int ar0  = aidx >> 2,       akq0 = aidx & 3;
    const int ar1  = (aidx + 1) >> 2, akq1 = (aidx + 1) & 3;
    const bool av0 = (ar0 < rows);
    const bool av1 = (ar1 < rows);

    const int bkk = tid >> 4;
    const int bn  = (tid & 15) * 4;

    float acc[8][4];
    #pragma unroll
    for (int i = 0; i < 8; ++i)
        #pragma unroll
        for (int j = 0; j < 4; ++j) acc[i][j] = 0.f;

    for (int k0 = 0; k0 < I_DIM; k0 += BK) {
        float4 va = av0
            ? *(const float4*)&g_act[(size_t)(row0 + ar0) * I_DIM + k0 + akq0 * 4]
            : make_float4(0.f, 0.f, 0.f, 0.f);
        float4 vb = av1
            ? *(const float4*)&g_act[(size_t)(row0 + ar1) * I_DIM + k0 + akq1 * 4]
            : make_float4(0.f, 0.f, 0.f, 0.f);
        float4 vB = *(const float4*)&dwe[(size_t)(k0 + bkk) * H_DIM + n0 + bn];

        __syncthreads();
        As[akq0 * 4 + 0][ar0] = va.x;
        As[akq0 * 4 + 1][ar0] = va.y;
        As[akq0 * 4 + 2][ar0] = va.z;
        As[akq0 * 4 + 3][ar0] = va.w;
        As[akq1 * 4 + 0][ar1] = vb.x;
        As[akq1 * 4 + 1][ar1] = vb.y;
        As[akq1 * 4 + 2][ar1] = vb.z;
        As[akq1 * 4 + 3][ar1] = vb.w;
        *(float4*)&Bs[bkk][bn] = vB;
        __syncthreads();

        #pragma unroll
        for (int kk = 0; kk < BK; ++kk) {
            float4 a0 = *(const float4*)&As[kk][rbase];
            float4 a1 = *(const float4*)&As[kk][rbase + 4];
            float4 b4 = *(const float4*)&Bs[kk][cbase];
            float a[8]  = {a0.x, a0.y, a0.z, a0.w, a1.x, a1.y, a1.z, a1.w};
            float bv[4] = {b4.x, b4.y, b4.z, b4.w};
            #pragma unroll
            for (int i = 0; i < 8; ++i)
                #pragma unroll
                for (int j = 0; j < 4; ++j)
                    acc[i][j] += a[i] * bv[j];
        }
    }

    // epilogue: weighted scatter-add (each out element receives exactly K=2 adds)
    #pragma unroll
    for (int i = 0; i < 8; ++i) {
        int r = rbase + i;
        if (r < rows) {
            float p = g_row_p[row0 + r];
            int   t = g_row_t[row0 + r];
            float* dst = &out[(size_t)t * H_DIM + n0 + cbase];
            #pragma unroll
            for (int j = 0; j < 4; ++j)
                atomicAdd(&dst[j], acc[i][j] * p);
        }
    }
}

// ---------------------------------------------------------------------------
extern "C" void kernel_launch(void* const* d_in, const int* in_sizes, int n_in,
                              void* d_out, int out_size) {
    const float* hid = (const float*)d_in[0];   // [T, H]
    const float* rw  = (const float*)d_in[1];   // [T, K]
    const int*   sel = (const int*)  d_in[2];   // [T, K]
    const float* gw  = (const float*)d_in[3];   // [E, H, I]
    const float* uw  = (const float*)d_in[4];   // [E, H, I]
    const float* dw  = (const float*)d_in[5];   // [E, I, H]
    float* out = (float*)d_out;                 // [T, H]

    k_zero_counts<<<1, 32>>>();
    k_hist<<<R_ROWS / 256, 256>>>(sel);
    k_prep<<<1, 1>>>();
    k_scatter<<<R_ROWS / 256, 256>>>(sel, rw);

    int n4 = (T_TOK * H_DIM) / 4;
    k_zero_out<<<n4 / 256, 256>>>((float4*)out, n4);

    dim3 g1(MAX_TILES, I_DIM / BN);   // 72 x 22
    k_gemm1<<<g1, 256>>>(hid, gw, uw);

    dim3 g2(MAX_TILES, H_DIM / BN);   // 72 x 32
    k_gemm2<<<g2, 256>>>(dw, out);
}

// round 2
// speedup vs baseline: 1.0001x; 1.0001x over previous
#include <cuda_runtime.h>
#include <math.h>

// ---------------------------------------------------------------------------
// MoE grouped MLP: T=4096 tokens, H=2048 hidden, I=1408 intermediate,
// E=8 experts, top-K=2.
//   rows = K*T = 8192 expanded rows, grouped by expert.
//   act  = silu(x @ gate_w[e]) * (x @ up_w[e])     [8192, I]
//   out[t] += prob * (act_row @ down_w[e])         [T, H]
// Round-1 baseline: fp32 SIMT tiled GEMMs + device-side permutation.
// ---------------------------------------------------------------------------

#define T_TOK 4096
#define H_DIM 2048
#define I_DIM 1408
#define N_EXP 8
#define TOPK  2
#define R_ROWS (T_TOK * TOPK)       // 8192

#define BM 128
#define BN 64
#define BK 16
#define MAX_TILES (R_ROWS / BM + N_EXP)   // 72 worst case

// ---- device-global scratch (no allocations allowed) ----
__device__ int   g_counts[N_EXP];
__device__ int   g_cursor[N_EXP];
__device__ int   g_tile_e[MAX_TILES];
__device__ int   g_tile_row0[MAX_TILES];
__device__ int   g_tile_rows[MAX_TILES];
__device__ int   g_num_tiles;
__device__ int   g_row_t[R_ROWS];         // source token per sorted row
__device__ float g_row_p[R_ROWS];         // router prob per sorted row
__device__ float g_act[R_ROWS * I_DIM];   // 46 MB intermediate activations

// ---------------------------------------------------------------------------
__global__ void k_zero_counts() {
    if (threadIdx.x < N_EXP) g_counts[threadIdx.x] = 0;
}

__global__ void k_hist(const int* __restrict__ sel) {
    int f = blockIdx.x * blockDim.x + threadIdx.x;
    if (f < R_ROWS) {
        int t = f % T_TOK;
        int k = f / T_TOK;
        atomicAdd(&g_counts[sel[t * TOPK + k]], 1);
    }
}

__global__ void k_prep() {
    // single thread: prefix sum over 8 experts + build ragged tile table
    int off = 0, nt = 0;
    for (int e = 0; e < N_EXP; ++e) {
        int c = g_counts[e];
        g_cursor[e] = off;
        for (int r0 = 0; r0 < c; r0 += BM) {
            g_tile_e[nt]    = e;
            g_tile_row0[nt] = off + r0;
            g_tile_rows[nt] = min(BM, c - r0);
            ++nt;
        }
        off += c;
    }
    g_num_tiles = nt;
}

__global__ void k_scatter(const int* __restrict__ sel,
                          const float* __restrict__ rw) {
    int f = blockIdx.x * blockDim.x + threadIdx.x;
    if (f < R_ROWS) {
        int t = f % T_TOK;
        int k = f / T_TOK;
        int e = sel[t * TOPK + k];
        int d = atomicAdd(&g_cursor[e], 1);
        g_row_t[d] = t;
        g_row_p[d] = rw[t * TOPK + k];
    }
}

__global__ void k_zero_out(float4* __restrict__ out, int n4) {
    int i = blockIdx.x * blockDim.x + threadIdx.x;
    if (i < n4) out[i] = make_float4(0.f, 0.f, 0.f, 0.f);
}

// ---------------------------------------------------------------------------
// GEMM1: fused gate+up.  C_g = A @ gate_w[e], C_u = A @ up_w[e],
// act = silu(C_g) * C_u.  A rows gathered from hidden_states via g_row_t.
// Block: BM x BN tile, 256 threads, 8x4 microtile per thread.
// ---------------------------------------------------------------------------
__global__ __launch_bounds__(256, 2)
void k_gemm1(const float* __restrict__ hid,
             const float* __restrict__ gw,
             const float* __restrict__ uw) {
    const int tile = blockIdx.x;
    if (tile >= g_num_tiles) return;
    const int e    = g_tile_e[tile];
    const int row0 = g_tile_row0[tile];
    const int rows = g_tile_rows[tile];
    const int n0   = blockIdx.y * BN;

    __shared__ float As[BK][BM];
    __shared__ float Bg[BK][BN];
    __shared__ float Bu[BK][BN];

    const int tid   = threadIdx.x;
    const int tx    = tid & 15;
    const int ty    = tid >> 4;
    const int rbase = ty * 8;
    const int cbase = tx * 4;

    const float* gwe = gw + (size_t)e * H_DIM * I_DIM;
    const float* uwe = uw + (size_t)e * H_DIM * I_DIM;

    // A-load mapping: each thread loads 2 float4s of the 128x16 A tile
    const int aidx  = tid * 2;
    const int ar0   = aidx >> 2,       akq0 = aidx & 3;
    const int ar1   = (aidx + 1) >> 2, akq1 = (aidx + 1) & 3;
    const int at0   = (ar0 < rows) ? g_row_t[row0 + ar0] : -1;
    const int at1   = (ar1 < rows) ? g_row_t[row0 + ar1] : -1;

    // B-load mapping: one float4 per thread per B matrix
    const int bkk = tid >> 4;
    const int bn  = (tid & 15) * 4;

    float accg[8][4], accu[8][4];
    #pragma unroll
    for (int i = 0; i < 8; ++i)
        #pragma unroll
        for (int j = 0; j < 4; ++j) { accg[i][j] = 0.f; accu[i][j] = 0.f; }

    for (int k0 = 0; k0 < H_DIM; k0 += BK) {
        float4 va = (at0 >= 0)
            ? *(const float4*)&hid[(size_t)at0 * H_DIM + k0 + akq0 * 4]
            : make_float4(0.f, 0.f, 0.f, 0.f);
        float4 vb = (at1 >= 0)
            ? *(const float4*)&hid[(size_t)at1 * H_DIM + k0 + akq1 * 4]
            : make_float4(0.f, 0.f, 0.f, 0.f);
        float4 vg = *(const float4*)&gwe[(size_t)(k0 + bkk) * I_DIM + n0 + bn];
        float4 vu = *(const float4*)&uwe[(size_t)(k0 + bkk) * I_DIM + n0 + bn];

        __syncthreads();   // previous iteration's compute done
        As[akq0 * 4 + 0][ar0] = va.x;
        As[akq0 * 4 + 1][ar0] = va.y;
        As[akq0 * 4 + 2][ar0] = va.z;
        As[akq0 * 4 + 3][ar0] = va.w;
        As[akq1 * 4 + 0][ar1] = vb.x;
        As[akq1 * 4 + 1][ar1] = vb.y;
        As[akq1 * 4 + 2][ar1] = vb.z;
        As[akq1 * 4 + 3][ar1] = vb.w;
        *(float4*)&Bg[bkk][bn] = vg;
        *(float4*)&Bu[bkk][bn] = vu;
        __syncthreads();

        #pragma unroll
        for (int kk = 0; kk < BK; ++kk) {
            float4 a0 = *(const float4*)&As[kk][rbase];
            float4 a1 = *(const float4*)&As[kk][rbase + 4];
            float4 g4 = *(const float4*)&Bg[kk][cbase];
            float4 u4 = *(const float4*)&Bu[kk][cbase];
            float a[8]  = {a0.x, a0.y, a0.z, a0.w, a1.x, a1.y, a1.z, a1.w};
            float gv[4] = {g4.x, g4.y, g4.z, g4.w};
            float uv[4] = {u4.x, u4.y, u4.z, u4.w};
            #pragma unroll
            for (int i = 0; i < 8; ++i)
                #pragma unroll
                for (int j = 0; j < 4; ++j) {
                    accg[i][j] += a[i] * gv[j];
                    accu[i][j] += a[i] * uv[j];
                }
        }
    }

    // epilogue: act = silu(g) * u
    #pragma unroll
    for (int i = 0; i < 8; ++i) {
        int r = rbase + i;
        if (r < rows) {
            float* dst = &g_act[(size_t)(row0 + r) * I_DIM + n0 + cbase];
            float4 o;
            float g, u;
            g = accg[i][0]; u = accu[i][0]; o.x = (g / (1.f + __expf(-g))) * u;
            g = accg[i][1]; u = accu[i][1]; o.y = (g / (1.f + __expf(-g))) * u;
            g = accg[i][2]; u = accu[i][2]; o.z = (g / (1.f + __expf(-g))) * u;
            g = accg[i][3]; u = accu[i][3]; o.w = (g / (1.f + __expf(-g))) * u;
            *(float4*)dst = o;
        }
    }
}

// ---------------------------------------------------------------------------
// GEMM2: down projection + weighted scatter-add into out.
//   C = act_rows @ down_w[e];  out[t, :] += prob * C_row
// ---------------------------------------------------------------------------
__global__ __launch_bounds__(256, 2)
void k_gemm2(const float* __restrict__ dw,
             float* __restrict__ out) {
    const int tile = blockIdx.x;
    if (tile >= g_num_tiles) return;
    const int e    = g_tile_e[tile];
    const int row0 = g_tile_row0[tile];
    const int rows = g_tile_rows[tile];
    const int n0   = blockIdx.y * BN;

    __shared__ float As[BK][BM];
    __shared__ float Bs[BK][BN];

    const int tid   = threadIdx.x;
    const int tx    = tid & 15;
    const int ty    = tid >> 4;
    const int rbase = ty * 8;
    const int cbase = tx * 4;

    const float* dwe = dw + (size_t)e * I_DIM * H_DIM;

    const int aidx = tid * 2;
    const int ar0  = aidx >> 2,       akq0 = aidx & 3;
    const int ar1  = (aidx + 1) >> 2, akq1 = (aidx + 1) & 3;
    const bool av0 = (ar0 < rows);
    const bool av1 = (ar1 < rows);

    const int bkk = tid >> 4;
    const int bn  = (tid & 15) * 4;

    float acc[8][4];
    #pragma unroll
    for (int i = 0; i < 8; ++i)
        #pragma unroll
        for (int j = 0; j < 4; ++j) acc[i][j] = 0.f;

    for (int k0 = 0; k0 < I_DIM; k0 += BK) {
        float4 va = av0
            ? *(const float4*)&g_act[(size_t)(row0 + ar0) * I_DIM + k0 + akq0 * 4]
            : make_float4(0.f, 0.f, 0.f, 0.f);
        float4 vb = av1
            ? *(const float4*)&g_act[(size_t)(row0 + ar1) * I_DIM + k0 + akq1 * 4]
            : make_float4(0.f, 0.f, 0.f, 0.f);
        float4 vB = *(const float4*)&dwe[(size_t)(k0 + bkk) * H_DIM + n0 + bn];

        __syncthreads();
        As[akq0 * 4 + 0][ar0] = va.x;
        As[akq0 * 4 + 1][ar0] = va.y;
        As[akq0 * 4 + 2][ar0] = va.z;
        As[akq0 * 4 + 3][ar0] = va.w;
        As[akq1 * 4 + 0][ar1] = vb.x;
        As[akq1 * 4 + 1][ar1] = vb.y;
        As[akq1 * 4 + 2][ar1] = vb.z;
        As[akq1 * 4 + 3][ar1] = vb.w;
        *(float4*)&Bs[bkk][bn] = vB;
        __syncthreads();

        #pragma unroll
        for (int kk = 0; kk < BK; ++kk) {
            float4 a0 = *(const float4*)&As[kk][rbase];
            float4 a1 = *(const float4*)&As[kk][rbase + 4];
            float4 b4 = *(const float4*)&Bs[kk][cbase];
            float a[8]  = {a0.x, a0.y, a0.z, a0.w, a1.x, a1.y, a1.z, a1.w};
            float bv[4] = {b4.x, b4.y, b4.z, b4.w};
            #pragma unroll
            for (int i = 0; i < 8; ++i)
                #pragma unroll
                for (int j = 0; j < 4; ++j)
                    acc[i][j] += a[i] * bv[j];
        }
    }

    // epilogue: weighted scatter-add (each out element receives exactly K=2 adds)
    #pragma unroll
    for (int i = 0; i < 8; ++i) {
        int r = rbase + i;
        if (r < rows) {
            float p = g_row_p[row0 + r];
            int   t = g_row_t[row0 + r];
            float* dst = &out[(size_t)t * H_DIM + n0 + cbase];
            #pragma unroll
            for (int j = 0; j < 4; ++j)
                atomicAdd(&dst[j], acc[i][j] * p);
        }
    }
}

// ---------------------------------------------------------------------------
extern "C" void kernel_launch(void* const* d_in, const int* in_sizes, int n_in,
                              void* d_out, int out_size) {
    const float* hid = (const float*)d_in[0];   // [T, H]
    const float* rw  = (const float*)d_in[1];   // [T, K]
    const int*   sel = (const int*)  d_in[2];   // [T, K]
    const float* gw  = (const float*)d_in[3];   // [E, H, I]
    const float* uw  = (const float*)d_in[4];   // [E, H, I]
    const float* dw  = (const float*)d_in[5];   // [E, I, H]
    float* out = (float*)d_out;                 // [T, H]

    k_zero_counts<<<1, 32>>>();
    k_hist<<<R_ROWS / 256, 256>>>(sel);
    k_prep<<<1, 1>>>();
    k_scatter<<<R_ROWS / 256, 256>>>(sel, rw);

    int n4 = (T_TOK * H_DIM) / 4;
    k_zero_out<<<n4 / 256, 256>>>((float4*)out, n4);

    dim3 g1(MAX_TILES, I_DIM / BN);   // 72 x 22
    k_gemm1<<<g1, 256>>>(hid, gw, uw);

    dim3 g2(MAX_TILES, H_DIM / BN);   // 72 x 32
    k_gemm2<<<g2, 256>>>(dw, out);
}